// round 16
// baseline (speedup 1.0000x reference)
#include <cuda_runtime.h>
#include <cuda_fp16.h>
#include <cstdint>

// CrossSpatialWindowAttention — fused fp16 mma, 1 window per 256-thread CTA,
// 3 CTAs/SM. Register-resident Q fragments; O-projection fused with store.
// This round: double-buffered B fragments (n24 sub-tiles) + float4 staging.

namespace {

constexpr int IMG     = 256;
constexpr int CQ      = 96;
constexpr int CKV     = 192;
constexpr int NH      = 6;
constexpr int WIN     = 64;
constexpr int THREADS = 256;

// weight-fragment table (uint4 = 2 k16-steps of fp16 B-fragment): [nt][k32][lane]
constexpr int FK_OFF = 0;
constexpr int FV_OFF = 2304;
constexpr int FQ_OFF = 4608;
constexpr int FO_OFF = 5760;
constexpr int F_TOTAL = 6912;
__device__ uint4 gWF[F_TOTAL];

// bias fragments: [head][m0/16][nt][lane] -> float4
constexpr int BF_TOTAL = NH * 4 * 8 * 32;   // 96KB
__device__ float4 gBF[BF_TOTAL];

// leading dims in halves: (LDH/8) odd -> conflict-free ldmatrix
constexpr int LDH_X  = 200;
constexpr int LDH_QK = 104;
constexpr int LDH_VT = 72;

// smem BYTE offsets (aliasing: O->XQ after death)
constexpr int OFF_XKV = 0;        // 25600
constexpr int OFF_XQ  = 25600;    // 13312; later O
constexpr int OFF_K   = 38912;    // 13312
constexpr int OFF_VT  = 52224;    // 13824
constexpr int OFF_BQ  = 66048;
constexpr int OFF_BK  = OFF_BQ + 384;
constexpr int OFF_BV  = OFF_BK + 384;
constexpr int OFF_BO  = OFF_BV + 384;
constexpr int SMEM_ALLOC = OFF_BO + 384;   // 67584 -> 3 CTAs/SM

__device__ __forceinline__ uint32_t smem_u32(const void* p) {
    return (uint32_t)__cvta_generic_to_shared(p);
}

__device__ __forceinline__ void ldsm4(uint32_t r[4], uint32_t addr) {
    asm volatile("ldmatrix.sync.aligned.m8n8.x4.shared.b16 {%0,%1,%2,%3}, [%4];"
                 : "=r"(r[0]), "=r"(r[1]), "=r"(r[2]), "=r"(r[3]) : "r"(addr));
}

__device__ __forceinline__ void mma16(float c[4], const uint32_t a[4],
                                      uint32_t b0, uint32_t b1) {
    asm volatile("mma.sync.aligned.m16n8k16.row.col.f32.f16.f16.f32 "
                 "{%0,%1,%2,%3},{%4,%5,%6,%7},{%8,%9},{%0,%1,%2,%3};"
                 : "+f"(c[0]), "+f"(c[1]), "+f"(c[2]), "+f"(c[3])
                 : "r"(a[0]), "r"(a[1]), "r"(a[2]), "r"(a[3]), "r"(b0), "r"(b1));
}

__device__ __forceinline__ uint32_t pack2(float a, float b) {
    __half2 h = __floats2half2_rn(a, b);
    return *reinterpret_cast<uint32_t*>(&h);
}

__device__ __forceinline__ uint32_t a_off16(int m0, int ldh, int lane) {
    const int row = m0 + (lane & 7) + ((lane >> 3) & 1) * 8;
    return (uint32_t)(row * ldh * 2 + ((lane >> 4) & 1) * 16);
}
__device__ __forceinline__ uint32_t b_off16(int n0, int ldh, int lane) {
    const int row = n0 + (lane & 7) + ((lane >> 4) & 1) * 8;
    return (uint32_t)(row * ldh * 2 + ((lane >> 3) & 1) * 16);
}

// ---- prep: pack weights into fp16 B-fragment order ----
__global__ void prep_kernel(const float* __restrict__ Wk, const float* __restrict__ Wv,
                            const float* __restrict__ Wq, const float* __restrict__ Wo) {
    const int idx = blockIdx.x * blockDim.x + threadIdx.x;
    if (idx >= F_TOTAL) return;
    const float* W; int K32, f;
    if (idx < FV_OFF)      { W = Wk; K32 = 6; f = idx; }
    else if (idx < FQ_OFF) { W = Wv; K32 = 6; f = idx - FV_OFF; }
    else if (idx < FO_OFF) { W = Wq; K32 = 3; f = idx - FQ_OFF; }
    else                   { W = Wo; K32 = 3; f = idx - FO_OFF; }
    const int lane = f & 31;
    const int kk   = (f >> 5) % K32;
    const int nt   = (f >> 5) / K32;
    const int g = lane >> 2, tig = lane & 3;
    const int col = nt * 8 + g;
    const int kb  = kk * 32;
    uint4 v;
    v.x = pack2(W[(kb +      2*tig) * 96 + col], W[(kb +      2*tig + 1) * 96 + col]);
    v.y = pack2(W[(kb +  8 + 2*tig) * 96 + col], W[(kb +  8 + 2*tig + 1) * 96 + col]);
    v.z = pack2(W[(kb + 16 + 2*tig) * 96 + col], W[(kb + 16 + 2*tig + 1) * 96 + col]);
    v.w = pack2(W[(kb + 24 + 2*tig) * 96 + col], W[(kb + 24 + 2*tig + 1) * 96 + col]);
    gWF[idx] = v;
}

// ---- prep: bias table in scores C-fragment order ----
__device__ __forceinline__ int rel_idx(int i, int j) {
    return ((i >> 3) - (j >> 3) + 7) * 15 + ((i & 7) - (j & 7) + 7);
}
__global__ void prep_bias(const float* __restrict__ bt) {
    const int idx = blockIdx.x * blockDim.x + threadIdx.x;
    if (idx >= BF_TOTAL) return;
    const int lane = idx & 31;
    const int nt   = (idx >> 5) & 7;
    const int m0g  = (idx >> 8) & 3;
    const int head = idx >> 10;
    const int g = lane >> 2, tig = lane & 3;
    const int i0 = m0g * 16 + g, i1 = i0 + 8;
    const int j0 = nt * 8 + 2 * tig;
    float4 v;
    v.x = bt[rel_idx(i0, j0)     * NH + head];
    v.y = bt[rel_idx(i0, j0 + 1) * NH + head];
    v.z = bt[rel_idx(i1, j0)     * NH + head];
    v.w = bt[rel_idx(i1, j0 + 1) * NH + head];
    gBF[idx] = v;
}

// GEMM sub-tile: m16 x n24, B double-buffered (prefetch distance 1).
// MODE 0: half2 row-major, 1: half transposed.
template <int K32, int LDAH, int MODE, int LDOUT>
__device__ __forceinline__ void gemm3(const __half* sA, const uint4* __restrict__ Wf,
                                      const float* __restrict__ bias, void* sOut,
                                      float scale, int m0, int ntb, int lane) {
    const int g = lane >> 2, tig = lane & 3;
    const uint32_t aAddr = smem_u32(sA) + a_off16(m0, LDAH, lane);
    const uint4* w0p = Wf + ((ntb + 0) * K32) * 32 + lane;
    const uint4* w1p = Wf + ((ntb + 1) * K32) * 32 + lane;
    const uint4* w2p = Wf + ((ntb + 2) * K32) * 32 + lane;

    float acc[3][4];
#pragma unroll
    for (int j = 0; j < 3; j++)
#pragma unroll
        for (int x = 0; x < 4; x++) acc[j][x] = 0.f;

    uint4 B[2][3];
    B[0][0] = w0p[0]; B[0][1] = w1p[0]; B[0][2] = w2p[0];

#pragma unroll
    for (int s = 0; s < K32; s++) {
        const int cur = s & 1, nxt = cur ^ 1;
        if (s + 1 < K32) {
            B[nxt][0] = w0p[(s + 1) * 32];
            B[nxt][1] = w1p[(s + 1) * 32];
            B[nxt][2] = w2p[(s + 1) * 32];
        }
        uint32_t Af0[4], Af1[4];
        ldsm4(Af0, aAddr + s * 64);
        ldsm4(Af1, aAddr + s * 64 + 32);
#pragma unroll
        for (int j = 0; j < 3; j++) {
            mma16(acc[j], Af0, B[cur][j].x, B[cur][j].y);
            mma16(acc[j], Af1, B[cur][j].z, B[cur][j].w);
        }
    }
#pragma unroll
    for (int j = 0; j < 3; j++) {
        const int col = (ntb + j) * 8 + 2 * tig;
        const float b0 = bias[col], b1 = bias[col + 1];
#pragma unroll
        for (int h = 0; h < 2; h++) {
            const int r = m0 + g + h * 8;
            const float v0 = (acc[j][2 * h + 0] + b0) * scale;
            const float v1 = (acc[j][2 * h + 1] + b1) * scale;
            if (MODE == 0) {
                *reinterpret_cast<__half2*>((__half*)sOut + r * LDOUT + col) =
                    __floats2half2_rn(v0, v1);
            } else {
                ((__half*)sOut)[col * LDOUT + r]       = __float2half_rn(v0);
                ((__half*)sOut)[(col + 1) * LDOUT + r] = __float2half_rn(v1);
            }
        }
    }
}

// O-projection sub-tile (m16 x n24, k=96) fused with global store, B double-buffered.
__device__ __forceinline__ void gemm_o_store3(const __half* sA,
                                              const uint4* __restrict__ Wf,
                                              const float* __restrict__ bo,
                                              float* __restrict__ out_b,
                                              int h0, int w0, int m0, int ntb, int lane) {
    const int g = lane >> 2, tig = lane & 3;
    const uint32_t aAddr = smem_u32(sA) + a_off16(m0, LDH_QK, lane);
    const uint4* w0p = Wf + ((ntb + 0) * 3) * 32 + lane;
    const uint4* w1p = Wf + ((ntb + 1) * 3) * 32 + lane;
    const uint4* w2p = Wf + ((ntb + 2) * 3) * 32 + lane;

    float acc[3][4];
#pragma unroll
    for (int j = 0; j < 3; j++)
#pragma unroll
        for (int x = 0; x < 4; x++) acc[j][x] = 0.f;

    uint4 B[2][3];
    B[0][0] = w0p[0]; B[0][1] = w1p[0]; B[0][2] = w2p[0];

#pragma unroll
    for (int s = 0; s < 3; s++) {
        const int cur = s & 1, nxt = cur ^ 1;
        if (s + 1 < 3) {
            B[nxt][0] = w0p[(s + 1) * 32];
            B[nxt][1] = w1p[(s + 1) * 32];
            B[nxt][2] = w2p[(s + 1) * 32];
        }
        uint32_t Af0[4], Af1[4];
        ldsm4(Af0, aAddr + s * 64);
        ldsm4(Af1, aAddr + s * 64 + 32);
#pragma unroll
        for (int j = 0; j < 3; j++) {
            mma16(acc[j], Af0, B[cur][j].x, B[cur][j].y);
            mma16(acc[j], Af1, B[cur][j].z, B[cur][j].w);
        }
    }
#pragma unroll
    for (int h = 0; h < 2; h++) {
        const int r = m0 + g + h * 8;
        const size_t pix = (size_t)(h0 + (r >> 3)) * IMG + (w0 + (r & 7));
#pragma unroll
        for (int j = 0; j < 3; j++) {
            const int col = (ntb + j) * 8 + 2 * tig;
            out_b[(size_t)col * (IMG * IMG) + pix]       = acc[j][2 * h + 0] + bo[col];
            out_b[(size_t)(col + 1) * (IMG * IMG) + pix] = acc[j][2 * h + 1] + bo[col + 1];
        }
    }
}

// vectorized staging: float4 loads (16B, aligned since w0 % 8 == 0), token-major fp16
template <int LDH>
__device__ __forceinline__ void stage_Xv(const float* __restrict__ img,
                                         __half* __restrict__ sX,
                                         int ch, int h0, int w0, int tid) {
    for (int idx = tid; idx < ch * 16; idx += THREADS) {
        const int c  = idx >> 4;
        const int tg = (idx >> 1) & 7;
        const int q  = idx & 1;
        const float4 v = *reinterpret_cast<const float4*>(
            img + (size_t)c * (IMG * IMG) + (size_t)(h0 + tg) * IMG + w0 + 4 * q);
        __half* dst = sX + (tg * 8 + 4 * q) * LDH + c;
        dst[0 * LDH] = __float2half_rn(v.x);
        dst[1 * LDH] = __float2half_rn(v.y);
        dst[2 * LDH] = __float2half_rn(v.z);
        dst[3 * LDH] = __float2half_rn(v.w);
    }
}

__global__ void __launch_bounds__(THREADS, 3)
xswa_kernel(const float* __restrict__ xq, const float* __restrict__ xkv,
            const float* __restrict__ bq, const float* __restrict__ bk,
            const float* __restrict__ bv, const float* __restrict__ bo,
            float* __restrict__ out) {
    extern __shared__ char smc[];
    const int tid  = threadIdx.x;
    const int warp = tid >> 5;
    const int lane = tid & 31;
    const int g = lane >> 2, tig = lane & 3;

    const int win = blockIdx.x;
    const int b   = win >> 10;
    const int rem = win & 1023;
    const int h0  = (rem >> 5) << 3;
    const int w0  = (rem & 31) << 3;

    __half* sXKV = reinterpret_cast<__half*>(smc + OFF_XKV);
    __half* sXQ  = reinterpret_cast<__half*>(smc + OFF_XQ);
    __half* sK   = reinterpret_cast<__half*>(smc + OFF_K);
    __half* sVT  = reinterpret_cast<__half*>(smc + OFF_VT);
    __half* sO   = reinterpret_cast<__half*>(smc + OFF_XQ);   // aliases XQ (dead)
    float*  sBQ  = reinterpret_cast<float*>(smc + OFF_BQ);
    float*  sBK  = reinterpret_cast<float*>(smc + OFF_BK);
    float*  sBV  = reinterpret_cast<float*>(smc + OFF_BV);
    float*  sBO  = reinterpret_cast<float*>(smc + OFF_BO);

    const float* xq_b  = xq  + (size_t)b * CQ  * (IMG * IMG);
    const float* xkv_b = xkv + (size_t)b * CKV * (IMG * IMG);
    float* out_b = out + (size_t)b * CQ * (IMG * IMG);

    // ---- stage (vectorized) ----
    if (tid < 96) {
        sBQ[tid] = bq[tid];
        sBK[tid] = bk[tid];
        sBV[tid] = bv[tid];
        sBO[tid] = bo[tid];
    }
    stage_Xv<LDH_X>(xkv_b, sXKV, CKV, h0, w0, tid);
    stage_Xv<LDH_QK>(xq_b, sXQ, CQ, h0, w0, tid);
    __syncthreads();

    // ---- K then V projections, 8 warps, 2x m16n24 double-buffered sub-tiles ----
    {
        const int m0  = (warp & 3) * 16;
        const int ntb = (warp >> 2) * 6;
        gemm3<6, LDH_X, 0, LDH_QK>(sXKV, gWF + FK_OFF, sBK, sK, 1.f, m0, ntb, lane);
        gemm3<6, LDH_X, 0, LDH_QK>(sXKV, gWF + FK_OFF, sBK, sK, 1.f, m0, ntb + 3, lane);
        gemm3<6, LDH_X, 1, LDH_VT>(sXKV, gWF + FV_OFF, sBV, sVT, 1.f, m0, ntb, lane);
        gemm3<6, LDH_X, 1, LDH_VT>(sXKV, gWF + FV_OFF, sBV, sVT, 1.f, m0, ntb + 3, lane);
    }

    // ---- Q projection for this warp's 3 attention slices, register-resident ----
    uint32_t Aq[3][4];
#pragma unroll
    for (int tt = 0; tt < 3; tt++) {
        const int slice = warp * 3 + tt;
        const int head = slice >> 2;
        const int m0   = (slice & 3) * 16;
        float qa[2][4];
#pragma unroll
        for (int j = 0; j < 2; j++)
#pragma unroll
            for (int x = 0; x < 4; x++) qa[j][x] = 0.f;
        const uint32_t aAddr = smem_u32(sXQ) + a_off16(m0, LDH_QK, lane);
        const uint4* wq = gWF + FQ_OFF + lane;
#pragma unroll
        for (int s = 0; s < 3; s++) {
            const uint4 B0 = wq[((2 * head    ) * 3 + s) * 32];
            const uint4 B1 = wq[((2 * head + 1) * 3 + s) * 32];
            uint32_t Af0[4], Af1[4];
            ldsm4(Af0, aAddr + s * 64);
            ldsm4(Af1, aAddr + s * 64 + 32);
            mma16(qa[0], Af0, B0.x, B0.y);
            mma16(qa[0], Af1, B0.z, B0.w);
            mma16(qa[1], Af0, B1.x, B1.y);
            mma16(qa[1], Af1, B1.z, B1.w);
        }
        const int c0 = head * 16 + 2 * tig;
        const int c1 = c0 + 8;
        const float b00 = sBQ[c0], b01 = sBQ[c0 + 1];
        const float b10 = sBQ[c1], b11 = sBQ[c1 + 1];
        Aq[tt][0] = pack2((qa[0][0] + b00) * 0.25f, (qa[0][1] + b01) * 0.25f);
        Aq[tt][1] = pack2((qa[0][2] + b00) * 0.25f, (qa[0][3] + b01) * 0.25f);
        Aq[tt][2] = pack2((qa[1][0] + b10) * 0.25f, (qa[1][1] + b11) * 0.25f);
        Aq[tt][3] = pack2((qa[1][2] + b10) * 0.25f, (qa[1][3] + b11) * 0.25f);
    }
    __syncthreads();   // K, VT ready; XQ dead (Aq in regs)

    // ---- attention: 24 (head, m16) slices, 3 per warp; Q from registers ----
#pragma unroll
    for (int tt = 0; tt < 3; tt++) {
        const int slice = warp * 3 + tt;
        const int head = slice >> 2;
        const int m0   = (slice & 3) * 16;

        // scores m16 x n64, k16
        float acc[8][4];
#pragma unroll
        for (int nt = 0; nt < 8; nt++)
#pragma unroll
            for (int x = 0; x < 4; x++) acc[nt][x] = 0.f;
#pragma unroll
        for (int jn = 0; jn < 4; jn++) {
            uint32_t Bf[4];
            ldsm4(Bf, smem_u32(sK) + b_off16(jn * 16, LDH_QK, lane) + head * 32);
            mma16(acc[2 * jn],     Aq[tt], Bf[0], Bf[1]);
            mma16(acc[2 * jn + 1], Aq[tt], Bf[2], Bf[3]);
        }

        // softmax in registers, bias via precomputed fragment table
        float rs0 = 0.f, rs1 = 0.f;
        {
            const float4* bfp = gBF + ((head * 4 + (m0 >> 4)) * 8) * 32 + lane;
#pragma unroll
            for (int nt = 0; nt < 8; nt++) {
                const float4 bf = bfp[nt * 32];
                acc[nt][0] = __expf(acc[nt][0] + bf.x);
                acc[nt][1] = __expf(acc[nt][1] + bf.y);
                acc[nt][2] = __expf(acc[nt][2] + bf.z);
                acc[nt][3] = __expf(acc[nt][3] + bf.w);
                rs0 += acc[nt][0] + acc[nt][1];
                rs1 += acc[nt][2] + acc[nt][3];
            }
            rs0 += __shfl_xor_sync(0xffffffffu, rs0, 1);
            rs0 += __shfl_xor_sync(0xffffffffu, rs0, 2);
            rs1 += __shfl_xor_sync(0xffffffffu, rs1, 1);
            rs1 += __shfl_xor_sync(0xffffffffu, rs1, 2);
            rs0 = 1.f / rs0;
            rs1 = 1.f / rs1;
        }

        // AV: k64 in 4 k16 chunks, A-frags packed from exp'd C regs
        float av[2][4];
#pragma unroll
        for (int j = 0; j < 2; j++)
#pragma unroll
            for (int x = 0; x < 4; x++) av[j][x] = 0.f;
        const uint32_t vb = smem_u32(sVT) + b_off16(head * 16, LDH_VT, lane);
#pragma unroll
        for (int j = 0; j < 4; j++) {
            uint32_t Bf[4];
            ldsm4(Bf, vb + j * 32);
            uint32_t af[4];
            af[0] = pack2(acc[2 * j][0],     acc[2 * j][1]);
            af[1] = pack2(acc[2 * j][2],     acc[2 * j][3]);
            af[2] = pack2(acc[2 * j + 1][0], acc[2 * j + 1][1]);
            af[3] = pack2(acc[2 * j + 1][2], acc[2 * j + 1][3]);
            mma16(av[0], af, Bf[0], Bf[1]);
            mma16(av[1], af, Bf[2], Bf[3]);
        }

        // normalize + write O (fp16, token-major; overwrites dead XQ)
#pragma unroll
        for (int j = 0; j < 2; j++) {
            const int col = head * 16 + j * 8 + 2 * tig;
            const int r0 = m0 + g;
            *reinterpret_cast<__half2*>(sO + r0 * LDH_QK + col) =
                __floats2half2_rn(av[j][0] * rs0, av[j][1] * rs0);
            *reinterpret_cast<__half2*>(sO + (r0 + 8) * LDH_QK + col) =
                __floats2half2_rn(av[j][2] * rs1, av[j][3] * rs1);
        }
    }
    __syncthreads();

    // ---- output projection fused with global store: 8 warps, 2x m16n24 ----
    {
        const int m0  = (warp & 3) * 16;
        const int ntb = (warp >> 2) * 6;
        gemm_o_store3(sO, gWF + FO_OFF, sBO, out_b, h0, w0, m0, ntb, lane);
        gemm_o_store3(sO, gWF + FO_OFF, sBO, out_b, h0, w0, m0, ntb + 3, lane);
    }
}

} // namespace

extern "C" void kernel_launch(void* const* d_in, const int* in_sizes, int n_in,
                              void* d_out, int out_size) {
    const float* xq   = (const float*)d_in[0];
    const float* xkv  = (const float*)d_in[1];
    const float* Wq   = (const float*)d_in[2];
    const float* bq   = (const float*)d_in[3];
    const float* Wk   = (const float*)d_in[4];
    const float* bk   = (const float*)d_in[5];
    const float* Wv   = (const float*)d_in[6];
    const float* bv   = (const float*)d_in[7];
    const float* bias_table = (const float*)d_in[8];
    const float* Wo   = (const float*)d_in[9];
    const float* bo   = (const float*)d_in[10];
    float* out = (float*)d_out;

    const int B = in_sizes[0] / (CQ * IMG * IMG);
    const int nwin = B * (IMG / 8) * (IMG / 8);

    prep_kernel<<<(F_TOTAL + 255) / 256, 256>>>(Wk, Wv, Wq, Wo);
    prep_bias<<<(BF_TOTAL + 255) / 256, 256>>>(bias_table);

    cudaFuncSetAttribute(xswa_kernel, cudaFuncAttributeMaxDynamicSharedMemorySize, SMEM_ALLOC);
    xswa_kernel<<<nwin, THREADS, SMEM_ALLOC>>>(xq, xkv, bq, bk, bv, bo, out);
}

// round 17
// speedup vs baseline: 1.0805x; 1.0805x over previous
#include <cuda_runtime.h>
#include <cuda_fp16.h>
#include <cstdint>

// CrossSpatialWindowAttention — fused fp16 mma, 1 window per 256-thread CTA,
// 3 CTAs/SM. Register-resident Q fragments (folded into K/V phase), bias-
// initialized score accumulators, single merged prep kernel.

namespace {

constexpr int IMG     = 256;
constexpr int CQ      = 96;
constexpr int CKV     = 192;
constexpr int NH      = 6;
constexpr int WIN     = 64;
constexpr int THREADS = 256;

// weight-fragment table (uint4 = 2 k16-steps of fp16 B-fragment): [nt][k32][lane]
constexpr int FK_OFF = 0;
constexpr int FV_OFF = 2304;
constexpr int FQ_OFF = 4608;
constexpr int FO_OFF = 5760;
constexpr int F_TOTAL = 6912;
__device__ uint4 gWF[F_TOTAL];

// bias fragments: [head][m0/16][nt][lane] -> float4
constexpr int BF_TOTAL = NH * 4 * 8 * 32;   // 96KB
__device__ float4 gBF[BF_TOTAL];

// leading dims in halves: (LDH/8) odd -> conflict-free ldmatrix
constexpr int LDH_X  = 200;
constexpr int LDH_QK = 104;
constexpr int LDH_VT = 72;
constexpr int LD_F   = 66;   // fp32; 96*66*4 = 25344 <= 25600

// smem BYTE offsets (aliasing: O->XQ, F->XKV after death)
constexpr int OFF_XKV = 0;        // 25600; later F (25344)
constexpr int OFF_XQ  = 25600;    // 13312; later O
constexpr int OFF_K   = 38912;    // 13312
constexpr int OFF_VT  = 52224;    // 13824
constexpr int OFF_BQ  = 66048;
constexpr int OFF_BK  = OFF_BQ + 384;
constexpr int OFF_BV  = OFF_BK + 384;
constexpr int OFF_BO  = OFF_BV + 384;
constexpr int SMEM_ALLOC = OFF_BO + 384;   // 67584 -> 3 CTAs/SM

__device__ __forceinline__ uint32_t smem_u32(const void* p) {
    return (uint32_t)__cvta_generic_to_shared(p);
}

__device__ __forceinline__ void ldsm4(uint32_t r[4], uint32_t addr) {
    asm volatile("ldmatrix.sync.aligned.m8n8.x4.shared.b16 {%0,%1,%2,%3}, [%4];"
                 : "=r"(r[0]), "=r"(r[1]), "=r"(r[2]), "=r"(r[3]) : "r"(addr));
}

__device__ __forceinline__ void mma16(float c[4], const uint32_t a[4],
                                      uint32_t b0, uint32_t b1) {
    asm volatile("mma.sync.aligned.m16n8k16.row.col.f32.f16.f16.f32 "
                 "{%0,%1,%2,%3},{%4,%5,%6,%7},{%8,%9},{%0,%1,%2,%3};"
                 : "+f"(c[0]), "+f"(c[1]), "+f"(c[2]), "+f"(c[3])
                 : "r"(a[0]), "r"(a[1]), "r"(a[2]), "r"(a[3]), "r"(b0), "r"(b1));
}

__device__ __forceinline__ uint32_t pack2(float a, float b) {
    __half2 h = __floats2half2_rn(a, b);
    return *reinterpret_cast<uint32_t*>(&h);
}

__device__ __forceinline__ uint32_t a_off16(int m0, int ldh, int lane) {
    const int row = m0 + (lane & 7) + ((lane >> 3) & 1) * 8;
    return (uint32_t)(row * ldh * 2 + ((lane >> 4) & 1) * 16);
}
__device__ __forceinline__ uint32_t b_off16(int n0, int ldh, int lane) {
    const int row = n0 + (lane & 7) + ((lane >> 4) & 1) * 8;
    return (uint32_t)(row * ldh * 2 + ((lane >> 3) & 1) * 16);
}

// ---- merged prep: weight fragments + bias fragments in one launch ----
__device__ __forceinline__ int rel_idx(int i, int j) {
    return ((i >> 3) - (j >> 3) + 7) * 15 + ((i & 7) - (j & 7) + 7);
}
__global__ void prep_all(const float* __restrict__ Wk, const float* __restrict__ Wv,
                         const float* __restrict__ Wq, const float* __restrict__ Wo,
                         const float* __restrict__ bt) {
    const int idx = blockIdx.x * blockDim.x + threadIdx.x;
    if (idx < F_TOTAL) {
        const float* W; int K32, f;
        if (idx < FV_OFF)      { W = Wk; K32 = 6; f = idx; }
        else if (idx < FQ_OFF) { W = Wv; K32 = 6; f = idx - FV_OFF; }
        else if (idx < FO_OFF) { W = Wq; K32 = 3; f = idx - FQ_OFF; }
        else                   { W = Wo; K32 = 3; f = idx - FO_OFF; }
        const int lane = f & 31;
        const int kk   = (f >> 5) % K32;
        const int nt   = (f >> 5) / K32;
        const int g = lane >> 2, tig = lane & 3;
        const int col = nt * 8 + g;
        const int kb  = kk * 32;
        uint4 v;
        v.x = pack2(W[(kb +      2*tig) * 96 + col], W[(kb +      2*tig + 1) * 96 + col]);
        v.y = pack2(W[(kb +  8 + 2*tig) * 96 + col], W[(kb +  8 + 2*tig + 1) * 96 + col]);
        v.z = pack2(W[(kb + 16 + 2*tig) * 96 + col], W[(kb + 16 + 2*tig + 1) * 96 + col]);
        v.w = pack2(W[(kb + 24 + 2*tig) * 96 + col], W[(kb + 24 + 2*tig + 1) * 96 + col]);
        gWF[idx] = v;
    } else if (idx < F_TOTAL + BF_TOTAL) {
        const int bidx = idx - F_TOTAL;
        const int lane = bidx & 31;
        const int nt   = (bidx >> 5) & 7;
        const int m0g  = (bidx >> 8) & 3;
        const int head = bidx >> 10;
        const int g = lane >> 2, tig = lane & 3;
        const int i0 = m0g * 16 + g, i1 = i0 + 8;
        const int j0 = nt * 8 + 2 * tig;
        float4 v;
        v.x = bt[rel_idx(i0, j0)     * NH + head];
        v.y = bt[rel_idx(i0, j0 + 1) * NH + head];
        v.z = bt[rel_idx(i1, j0)     * NH + head];
        v.w = bt[rel_idx(i1, j0 + 1) * NH + head];
        gBF[bidx] = v;
    }
}

// GEMM: m16 x n(8*NT) warp tile, A fp16 smem (ldsm), B frags via LDG.128.
// MODE 0: half2 row-major, 1: half transposed, 2: f32 transposed.
template <int NT, int K32, int LDAH, int MODE, int LDOUT>
__device__ __forceinline__ void gemm_h(const __half* sA, const uint4* __restrict__ Wf,
                                       const float* __restrict__ bias, void* sOut,
                                       float scale, int m0, int ntb, int lane) {
    const int g = lane >> 2, tig = lane & 3;
    const uint32_t aAddr = smem_u32(sA) + a_off16(m0, LDAH, lane);
    const uint4* wbase = Wf + lane;

    float acc[NT][4];
#pragma unroll
    for (int j = 0; j < NT; j++)
#pragma unroll
        for (int x = 0; x < 4; x++) acc[j][x] = 0.f;

#pragma unroll
    for (int s = 0; s < K32; s++) {
        uint4 B[NT];
#pragma unroll
        for (int j = 0; j < NT; j++) B[j] = wbase[((ntb + j) * K32 + s) * 32];
        uint32_t Af0[4], Af1[4];
        ldsm4(Af0, aAddr + s * 64);
        ldsm4(Af1, aAddr + s * 64 + 32);
#pragma unroll
        for (int j = 0; j < NT; j++) {
            mma16(acc[j], Af0, B[j].x, B[j].y);
            mma16(acc[j], Af1, B[j].z, B[j].w);
        }
    }
#pragma unroll
    for (int j = 0; j < NT; j++) {
        const int col = (ntb + j) * 8 + 2 * tig;
        const float b0 = bias[col], b1 = bias[col + 1];
#pragma unroll
        for (int h = 0; h < 2; h++) {
            const int r = m0 + g + h * 8;
            const float v0 = (acc[j][2 * h + 0] + b0) * scale;
            const float v1 = (acc[j][2 * h + 1] + b1) * scale;
            if (MODE == 0) {
                *reinterpret_cast<__half2*>((__half*)sOut + r * LDOUT + col) =
                    __floats2half2_rn(v0, v1);
            } else if (MODE == 1) {
                ((__half*)sOut)[col * LDOUT + r]       = __float2half_rn(v0);
                ((__half*)sOut)[(col + 1) * LDOUT + r] = __float2half_rn(v1);
            } else {
                ((float*)sOut)[col * LDOUT + r]       = v0;
                ((float*)sOut)[(col + 1) * LDOUT + r] = v1;
            }
        }
    }
}

// conflict-free staging: lane -> (4 channels x 8 tokens)
template <int LDH>
__device__ __forceinline__ void stage_Xh(const float* __restrict__ img,
                                         __half* __restrict__ sX,
                                         int ch, int h0, int w0, int warp, int lane) {
    const int u = lane & 7;
    const int v = lane >> 3;
    for (int it = warp; it < ch * 2; it += 8) {
        const int cg = it >> 3, tg = it & 7;
        const int c = cg * 4 + v;
        const float val = img[(size_t)c * (IMG * IMG) + (size_t)(h0 + tg) * IMG + w0 + u];
        sX[(tg * 8 + u) * LDH + c] = __float2half_rn(val);
    }
}

__global__ void __launch_bounds__(THREADS, 3)
xswa_kernel(const float* __restrict__ xq, const float* __restrict__ xkv,
            const float* __restrict__ bq, const float* __restrict__ bk,
            const float* __restrict__ bv, const float* __restrict__ bo,
            float* __restrict__ out) {
    extern __shared__ char smc[];
    const int tid  = threadIdx.x;
    const int warp = tid >> 5;
    const int lane = tid & 31;
    const int g = lane >> 2, tig = lane & 3;

    const int win = blockIdx.x;
    const int b   = win >> 10;
    const int rem = win & 1023;
    const int h0  = (rem >> 5) << 3;
    const int w0  = (rem & 31) << 3;

    __half* sXKV = reinterpret_cast<__half*>(smc + OFF_XKV);
    __half* sXQ  = reinterpret_cast<__half*>(smc + OFF_XQ);
    __half* sK   = reinterpret_cast<__half*>(smc + OFF_K);
    __half* sVT  = reinterpret_cast<__half*>(smc + OFF_VT);
    __half* sO   = reinterpret_cast<__half*>(smc + OFF_XQ);   // aliases XQ (dead)
    float*  sF   = reinterpret_cast<float*>(smc + OFF_XKV);   // aliases XKV (dead)
    float*  sBQ  = reinterpret_cast<float*>(smc + OFF_BQ);
    float*  sBK  = reinterpret_cast<float*>(smc + OFF_BK);
    float*  sBV  = reinterpret_cast<float*>(smc + OFF_BV);
    float*  sBO  = reinterpret_cast<float*>(smc + OFF_BO);

    const float* xq_b  = xq  + (size_t)b * CQ  * (IMG * IMG);
    const float* xkv_b = xkv + (size_t)b * CKV * (IMG * IMG);

    // ---- stage ----
    if (tid < 96) {
        sBQ[tid] = bq[tid];
        sBK[tid] = bk[tid];
        sBV[tid] = bv[tid];
        sBO[tid] = bo[tid];
    }
    stage_Xh<LDH_X>(xkv_b, sXKV, CKV, h0, w0, warp, lane);
    stage_Xh<LDH_QK>(xq_b, sXQ, CQ, h0, w0, warp, lane);
    __syncthreads();

    // ---- K then V projections, 8 warps m16n48 each ----
    gemm_h<6, 6, LDH_X, 0, LDH_QK>(
        sXKV, gWF + FK_OFF, sBK, sK, 1.f, (warp & 3) * 16, (warp >> 2) * 6, lane);
    gemm_h<6, 6, LDH_X, 1, LDH_VT>(
        sXKV, gWF + FV_OFF, sBV, sVT, 1.f, (warp & 3) * 16, (warp >> 2) * 6, lane);

    // ---- Q projection for this warp's 3 attention slices, register-resident ----
    uint32_t Aq[3][4];
#pragma unroll
    for (int tt = 0; tt < 3; tt++) {
        const int slice = warp * 3 + tt;
        const int head = slice >> 2;
        const int m0   = (slice & 3) * 16;
        float qa[2][4];
#pragma unroll
        for (int j = 0; j < 2; j++)
#pragma unroll
            for (int x = 0; x < 4; x++) qa[j][x] = 0.f;
        const uint32_t aAddr = smem_u32(sXQ) + a_off16(m0, LDH_QK, lane);
        const uint4* wq = gWF + FQ_OFF + lane;
#pragma unroll
        for (int s = 0; s < 3; s++) {
            const uint4 B0 = wq[((2 * head    ) * 3 + s) * 32];
            const uint4 B1 = wq[((2 * head + 1) * 3 + s) * 32];
            uint32_t Af0[4], Af1[4];
            ldsm4(Af0, aAddr + s * 64);
            ldsm4(Af1, aAddr + s * 64 + 32);
            mma16(qa[0], Af0, B0.x, B0.y);
            mma16(qa[0], Af1, B0.z, B0.w);
            mma16(qa[1], Af0, B1.x, B1.y);
            mma16(qa[1], Af1, B1.z, B1.w);
        }
        const int c0 = head * 16 + 2 * tig;
        const int c1 = c0 + 8;
        const float b00 = sBQ[c0], b01 = sBQ[c0 + 1];
        const float b10 = sBQ[c1], b11 = sBQ[c1 + 1];
        Aq[tt][0] = pack2((qa[0][0] + b00) * 0.25f, (qa[0][1] + b01) * 0.25f);
        Aq[tt][1] = pack2((qa[0][2] + b00) * 0.25f, (qa[0][3] + b01) * 0.25f);
        Aq[tt][2] = pack2((qa[1][0] + b10) * 0.25f, (qa[1][1] + b11) * 0.25f);
        Aq[tt][3] = pack2((qa[1][2] + b10) * 0.25f, (qa[1][3] + b11) * 0.25f);
    }
    __syncthreads();   // K, VT ready; XQ dead (Aq in regs)

    // ---- attention: 24 (head, m16) slices, 3 per warp; Q from registers ----
#pragma unroll
    for (int tt = 0; tt < 3; tt++) {
        const int slice = warp * 3 + tt;
        const int head = slice >> 2;
        const int m0   = (slice & 3) * 16;

        // scores m16 x n64, k16 — accumulators INITIALIZED WITH BIAS fragments
        float acc[8][4];
        {
            const float4* bfp = gBF + ((head * 4 + (m0 >> 4)) * 8) * 32 + lane;
#pragma unroll
            for (int nt = 0; nt < 8; nt++) {
                const float4 bf = bfp[nt * 32];
                acc[nt][0] = bf.x;
                acc[nt][1] = bf.y;
                acc[nt][2] = bf.z;
                acc[nt][3] = bf.w;
            }
        }
#pragma unroll
        for (int jn = 0; jn < 4; jn++) {
            uint32_t Bf[4];
            ldsm4(Bf, smem_u32(sK) + b_off16(jn * 16, LDH_QK, lane) + head * 32);
            mma16(acc[2 * jn],     Aq[tt], Bf[0], Bf[1]);
            mma16(acc[2 * jn + 1], Aq[tt], Bf[2], Bf[3]);
        }

        // softmax in registers
        float rs0 = 0.f, rs1 = 0.f;
#pragma unroll
        for (int nt = 0; nt < 8; nt++) {
            acc[nt][0] = __expf(acc[nt][0]);
            acc[nt][1] = __expf(acc[nt][1]);
            acc[nt][2] = __expf(acc[nt][2]);
            acc[nt][3] = __expf(acc[nt][3]);
            rs0 += acc[nt][0] + acc[nt][1];
            rs1 += acc[nt][2] + acc[nt][3];
        }
        rs0 += __shfl_xor_sync(0xffffffffu, rs0, 1);
        rs0 += __shfl_xor_sync(0xffffffffu, rs0, 2);
        rs1 += __shfl_xor_sync(0xffffffffu, rs1, 1);
        rs1 += __shfl_xor_sync(0xffffffffu, rs1, 2);
        rs0 = 1.f / rs0;
        rs1 = 1.f / rs1;

        // AV: k64 in 4 k16 chunks, A-frags packed from exp'd C regs
        float av[2][4];
#pragma unroll
        for (int j = 0; j < 2; j++)
#pragma unroll
            for (int x = 0; x < 4; x++) av[j][x] = 0.f;
        const uint32_t vb = smem_u32(sVT) + b_off16(head * 16, LDH_VT, lane);
#pragma unroll
        for (int j = 0; j < 4; j++) {
            uint32_t Bf[4];
            ldsm4(Bf, vb + j * 32);
            uint32_t af[4];
            af[0] = pack2(acc[2 * j][0],     acc[2 * j][1]);
            af[1] = pack2(acc[2 * j][2],     acc[2 * j][3]);
            af[2] = pack2(acc[2 * j + 1][0], acc[2 * j + 1][1]);
            af[3] = pack2(acc[2 * j + 1][2], acc[2 * j + 1][3]);
            mma16(av[0], af, Bf[0], Bf[1]);
            mma16(av[1], af, Bf[2], Bf[3]);
        }

        // normalize + write O (fp16, token-major; overwrites dead XQ)
#pragma unroll
        for (int j = 0; j < 2; j++) {
            const int col = head * 16 + j * 8 + 2 * tig;
            const int r0 = m0 + g;
            *reinterpret_cast<__half2*>(sO + r0 * LDH_QK + col) =
                __floats2half2_rn(av[j][0] * rs0, av[j][1] * rs0);
            *reinterpret_cast<__half2*>(sO + (r0 + 8) * LDH_QK + col) =
                __floats2half2_rn(av[j][2] * rs1, av[j][3] * rs1);
        }
    }
    __syncthreads();

    // ---- output projection: 8 warps m16n48 -> F fp32 [96][64] (aliases XKV) ----
    gemm_h<6, 3, LDH_QK, 2, LD_F>(
        sO, gWF + FO_OFF, sBO, sF, 1.f, (warp & 3) * 16, (warp >> 2) * 6, lane);
    __syncthreads();

    // ---- coalesced store ----
    {
        float* out_b = out + (size_t)b * CQ * (IMG * IMG);
#pragma unroll
        for (int idx = tid; idx < CQ * WIN / 2; idx += THREADS) {
            const int c  = idx >> 5;
            const int t0 = (idx & 31) * 2;
            const float2 v = *reinterpret_cast<const float2*>(&sF[c * LD_F + t0]);
            float* dst = out_b + (size_t)c * (IMG * IMG)
                       + (size_t)(h0 + (t0 >> 3)) * IMG + (w0 + (t0 & 7));
            *reinterpret_cast<float2*>(dst) = v;
        }
    }
}

} // namespace

extern "C" void kernel_launch(void* const* d_in, const int* in_sizes, int n_in,
                              void* d_out, int out_size) {
    const float* xq   = (const float*)d_in[0];
    const float* xkv  = (const float*)d_in[1];
    const float* Wq   = (const float*)d_in[2];
    const float* bq   = (const float*)d_in[3];
    const float* Wk   = (const float*)d_in[4];
    const float* bk   = (const float*)d_in[5];
    const float* Wv   = (const float*)d_in[6];
    const float* bv   = (const float*)d_in[7];
    const float* bias_table = (const float*)d_in[8];
    const float* Wo   = (const float*)d_in[9];
    const float* bo   = (const float*)d_in[10];
    float* out = (float*)d_out;

    const int B = in_sizes[0] / (CQ * IMG * IMG);
    const int nwin = B * (IMG / 8) * (IMG / 8);

    prep_all<<<(F_TOTAL + BF_TOTAL + 255) / 256, 256>>>(Wk, Wv, Wq, Wo, bias_table);

    cudaFuncSetAttribute(xswa_kernel, cudaFuncAttributeMaxDynamicSharedMemorySize, SMEM_ALLOC);
    xswa_kernel<<<nwin, THREADS, SMEM_ALLOC>>>(xq, xkv, bq, bk, bv, bo, out);
}